// round 13
// baseline (speedup 1.0000x reference)
#include <cuda_runtime.h>
#include <cuda_bf16.h>
#include <math.h>
#include <stdint.h>

#define NF   48
#define NM   51
#define IMG  256
#define TABN 2049

// ---- dynamic smem layout (bytes) ----
#define XCPY    10944           // one shifted x copy: 76 rows * 72 halves * 2B
#define B1P_OFF 21888           // 768 uint2 = 6144
#define B2P_OFF 28032           // 672 uint2 = 5376
#define G_OFF   33408           // ring: 24 * GROWR = 178176
#define GROWR   7424            // 64 px * 116B
#define RED_OFF 211584
#define SMEM_TOTAL 211712

// ---- device scratch ----
__device__ __align__(16) __nv_bfloat16 g_B1[NF * 64];   // [f][k=p*8+q]
__device__ __align__(16) __nv_bfloat16 g_B2[64 * 64];   // [n=p*8+q][f] (f>=48 zero)
__device__ __align__(16) uint2 g_B1p[768];              // frag-ordered: (k*6+n)*32+lane
__device__ __align__(16) uint2 g_B2p[672];              // frag-ordered: (k*7+n)*32+lane
__device__ float2 g_tab[NF * TABN];
__device__ float  g_r[16 * IMG * IMG];
__device__ float  g_partial[16 * 20];

__device__ __forceinline__ void mma_bf16(float c[4], const uint32_t a[4],
                                         uint32_t b0, uint32_t b1) {
    asm volatile("mma.sync.aligned.m16n8k16.row.col.f32.bf16.bf16.f32 "
        "{%0,%1,%2,%3}, {%4,%5,%6,%7}, {%8,%9}, {%0,%1,%2,%3};"
        : "+f"(c[0]), "+f"(c[1]), "+f"(c[2]), "+f"(c[3])
        : "r"(a[0]), "r"(a[1]), "r"(a[2]), "r"(a[3]), "r"(b0), "r"(b1));
}
__device__ __forceinline__ uint32_t bfpk(float hi, float lo) {
    uint32_t r; asm("cvt.rn.bf16x2.f32 %0, %1, %2;" : "=r"(r) : "f"(hi), "f"(lo)); return r;
}

// ---------------- K1: normalize weights -> B1/B2 bf16 + RBF tables ----------------
__global__ void prep_kernel(const float* __restrict__ cw, const float* __restrict__ sf,
                            const float* __restrict__ rbw, const float* __restrict__ rbc) {
    __shared__ float wn[49];
    __shared__ float msh[2];
    __shared__ float wsh[NM], csh[NM];
    __shared__ float tsh[TABN];
    int f = blockIdx.x, tid = threadIdx.x;

    if (tid < 49) wn[tid] = cw[f * 49 + tid];
    if (tid < NM) { wsh[tid] = rbw[f * NM + tid]; csh[tid] = rbc[tid]; }
    __syncthreads();
    if (tid == 0) {
        float mean = 0.f;
        #pragma unroll
        for (int i = 0; i < 49; i++) mean += wn[i];
        mean *= (1.f / 49.f);
        float ssq = 0.f;
        #pragma unroll
        for (int i = 0; i < 49; i++) { float d = wn[i] - mean; ssq += d * d; }
        msh[0] = mean;
        msh[1] = sf[f] / (sqrtf(ssq) + 1e-12f);
    }
    __syncthreads();
    if (tid < 49) wn[tid] = (wn[tid] - msh[0]) * msh[1];
    __syncthreads();
    if (tid < 64) {
        int p = tid >> 3, q = tid & 7;
        float v = (p < 7 && q < 7) ? wn[p * 7 + q] : 0.f;
        g_B1[f * 64 + tid] = __float2bfloat16(v);   // [f][k]
        g_B2[tid * 64 + f] = __float2bfloat16(v);   // [n][f]
    }
    for (int k = tid; k < TABN; k += blockDim.x) {
        float z = -16.f + (float)k * (1.f / 64.f);
        float acc = 0.f;
        #pragma unroll
        for (int m = 0; m < NM; m++) {
            float d = z - csh[m];
            acc += wsh[m] * __expf(-0.01f * d * d);
        }
        tsh[k] = acc;
    }
    __syncthreads();
    for (int k = tid; k < TABN; k += blockDim.x) {
        float v = tsh[k];
        float dl = (k < TABN - 1) ? (tsh[k + 1] - v) : 0.f;
        g_tab[f * TABN + k] = make_float2(v, dl);
    }
}

// ---------------- K1b: pack B matrices into mma-fragment order ----------------
__global__ void pack_kernel() {
    int i = threadIdx.x;          // 768 threads
    {
        int lane = i & 31, kn = i >> 5;      // kn < 24
        int k = kn / 6, n = kn - k * 6;
        int g = lane >> 2, tg = lane & 3;
        const uint32_t* row = (const uint32_t*)(g_B1 + (n * 8 + g) * 64);
        uint2 v;
        v.x = row[(k * 16 + tg * 2) >> 1];
        v.y = row[(k * 16 + tg * 2 + 8) >> 1];
        g_B1p[i] = v;
    }
    if (i < 672) {
        int lane = i & 31, kn = i >> 5;      // kn < 21
        int k = kn / 7, n = kn - k * 7;
        int g = lane >> 2, tg = lane & 3;
        const uint32_t* row = (const uint32_t*)(g_B2 + (n * 8 + g) * 64);
        uint2 v;
        v.x = row[(k * 16 + tg * 2) >> 1];
        v.y = row[(k * 16 + tg * 2 + 8) >> 1];
        g_B2p[i] = v;
    }
}

__global__ void dummy_kernel() {}

// ---------------- K2: fused tensor-core main (mma.sync, ring-24, 1 barrier/slab) ----------------
// grid 320 = 16 img x 4 ytiles x 5 xtiles; 512 threads
__global__ void __launch_bounds__(512)
main_kernel(const float* __restrict__ input, const float* __restrict__ net_input) {
    extern __shared__ __align__(16) char smem[];

    int bid = blockIdx.x;
    int img = bid / 20;
    int rr  = bid % 20;
    int y0 = (rr / 5) * 64;
    int x0 = (rr % 5) * 58;
    int tid  = threadIdx.x;
    int wid  = tid >> 5;
    int lane = tid & 31;

    const float* ibase = input + img * IMG * IMG;
    const float* nbase = net_input + img * IMG * IMG;

    // ---- stage x halo: 2 shifted bf16 copies (76 rows x 71 cols) ----
    __nv_bfloat16* xs0 = (__nv_bfloat16*)smem;
    __nv_bfloat16* xs1 = (__nv_bfloat16*)(smem + XCPY);
    for (int idx = tid; idx < 76 * 71; idx += 512) {
        int xr = idx / 71, xc = idx - xr * 71;
        int gy = y0 - 6 + xr, gx = x0 - 6 + xc;
        gy = (gy < 0) ? (-1 - gy) : ((gy >= IMG) ? (2 * IMG - 1 - gy) : gy);
        gx = (gx < 0) ? (-1 - gx) : ((gx >= IMG) ? (2 * IMG - 1 - gx) : gx);
        __nv_bfloat16 v = __float2bfloat16(ibase[gy * IMG + gx]);
        xs0[xr * 72 + xc] = v;
        if (xc >= 1) xs1[xr * 72 + xc - 1] = v;
    }
    // ---- stage packed B fragments ----
    {
        uint2* d1p = (uint2*)(smem + B1P_OFF);
        uint2* d2p = (uint2*)(smem + B2P_OFF);
        for (int i = tid; i < 768; i += 512) d1p[i] = g_B1p[i];
        for (int i = tid; i < 672; i += 512) d2p[i] = g_B2p[i];
    }
    __syncthreads();

    int g  = lane >> 2;       // 0..7
    int tg = lane & 3;        // 0..3
    float ss = 0.f;

    // worker constants
    int ca0  = (wid & 1) * 32;
    int roct = wid >> 1;                 // 0..7
    const char* xc = smem + (g & 1) * XCPY;
    int colb = ca0 + 2 * tg + g - (g & 1);   // + m*16 per m, in halves
    const uint2* bp1 = (const uint2*)(smem + B1P_OFF) + lane;
    const uint2* bp2 = (const uint2*)(smem + B2P_OFF) + lane;

    // gather constants
    int xl = tid & 63;
    int yh = tid >> 6;                   // 0..7

    int rslot = roct;                    // (8s + roct) % 24, produce slot
    int gbase = yh + 6 - 16;             // (8(s-2)+yh+6) % 24 tracker (valid from s>=2)

    #pragma unroll 1
    for (int s = 0; s < 10; s++) {
        __syncthreads();   // all produce of slab s-1 visible; ring slots disjoint otherwise

        // ---- gather first (lag 2): out rows 8(s-2)+yh, reads G rows [8s-16, 8s-3] ----
        if (s >= 2) {
            int yl = 8 * (s - 2) + yh;
            int xg = x0 + xl;
            if (xl < 58 && xg < IMG) {
                float cv = 0.f;
                #pragma unroll
                for (int p = 0; p < 7; p++) {
                    int sl = gbase - p;
                    if (sl < 0) sl += 24;
                    const char* rb = smem + G_OFF + sl * GROWR + p * 16;
                    #pragma unroll
                    for (int q = 0; q < 7; q++) {
                        uint16_t gv = *(const uint16_t*)(rb + (xl + 6 - q) * 116 + q * 2);
                        cv += __uint_as_float((uint32_t)gv << 16);
                    }
                }
                int yg = y0 + yl;
                float iv = ibase[yg * IMG + xg];
                float nv = nbase[yg * IMG + xg];
                float rv = iv - cv - nv;
                g_r[img * IMG * IMG + yg * IMG + xg] = rv;
                ss += rv * rv;
            }
        }

        // ---- produce slab s: a-rows 8s..8s+7 (this warp: ra = 8s+roct) ----
        int ra = 8 * s + roct;
        if (ra < 70) {
            // GEMM1: D1[32px x 48f], A frags direct from x copies
            float d1[2][6][4];
            #pragma unroll
            for (int m = 0; m < 2; m++)
                #pragma unroll
                for (int n = 0; n < 6; n++)
                    #pragma unroll
                    for (int e = 0; e < 4; e++) d1[m][n][e] = 0.f;
            #pragma unroll
            for (int k = 0; k < 4; k++) {
                uint32_t afr[2][4];
                #pragma unroll
                for (int m = 0; m < 2; m++) {
                    const char* ab = xc + (((ra + 2 * k) * 72) + colb + m * 16) * 2;
                    afr[m][0] = *(const uint32_t*)ab;
                    afr[m][1] = *(const uint32_t*)(ab + 16);
                    if (k < 3) {
                        afr[m][2] = *(const uint32_t*)(ab + 144);
                        afr[m][3] = *(const uint32_t*)(ab + 160);
                    } else {
                        afr[m][2] = 0u; afr[m][3] = 0u;   // k>=56 hits zero B cols
                    }
                }
                #pragma unroll
                for (int n = 0; n < 6; n++) {
                    uint2 b01 = bp1[(k * 6 + n) * 32];
                    mma_bf16(d1[0][n], afr[0], b01.x, b01.y);
                    mma_bf16(d1[1][n], afr[1], b01.x, b01.y);
                }
            }

            // RBF lerp in-register via global table (+ zero outside image)
            int u = y0 - 3 + ra;
            bool uok = (u >= 0) && (u < IMG);
            #pragma unroll
            for (int m = 0; m < 2; m++) {
                int vA = x0 - 3 + ca0 + m * 16 + g;
                int vB = vA + 8;
                bool okA = uok && (vA >= 0) && (vA < IMG);
                bool okB = uok && (vB >= 0) && (vB < IMG);
                #pragma unroll
                for (int n = 0; n < 6; n++) {
                    #pragma unroll
                    for (int e = 0; e < 4; e++) {
                        bool ok = (e < 2) ? okA : okB;
                        int fidx = n * 8 + tg * 2 + (e & 1);
                        float z = d1[m][n][e];
                        float t = fminf(fmaxf((z + 16.f) * 64.f, 0.f), 2047.99f);
                        int ix = (int)t;
                        float fr = t - (float)ix;
                        float2 tv = __ldg(&g_tab[fidx * TABN + ix]);
                        float a = tv.x + fr * tv.y;
                        d1[m][n][e] = ok ? a : 0.f;
                    }
                }
            }

            // repack D1 -> A fragments of GEMM2 (register-only)
            uint32_t a2[2][3][4];
            #pragma unroll
            for (int m = 0; m < 2; m++)
                #pragma unroll
                for (int t = 0; t < 3; t++) {
                    a2[m][t][0] = bfpk(d1[m][2 * t][1],     d1[m][2 * t][0]);
                    a2[m][t][1] = bfpk(d1[m][2 * t][3],     d1[m][2 * t][2]);
                    a2[m][t][2] = bfpk(d1[m][2 * t + 1][1], d1[m][2 * t + 1][0]);
                    a2[m][t][3] = bfpk(d1[m][2 * t + 1][3], d1[m][2 * t + 1][2]);
                }

            // GEMM2: G[32px x 56n] = A2[32x48] * B2[48x56]
            float d2[2][7][4];
            #pragma unroll
            for (int m = 0; m < 2; m++)
                #pragma unroll
                for (int n = 0; n < 7; n++)
                    #pragma unroll
                    for (int e = 0; e < 4; e++) d2[m][n][e] = 0.f;
            #pragma unroll
            for (int k = 0; k < 3; k++) {
                #pragma unroll
                for (int n = 0; n < 7; n++) {
                    uint2 b01 = bp2[(k * 7 + n) * 32];
                    mma_bf16(d2[0][n], a2[0][k], b01.x, b01.y);
                    mma_bf16(d2[1][n], a2[1][k], b01.x, b01.y);
                }
            }

            // store G ring (bf16, px stride 116B, ring slot rslot)
            char* grow = smem + G_OFF + rslot * GROWR;
            #pragma unroll
            for (int m = 0; m < 2; m++) {
                int pxA = ca0 + m * 16 + g;
                #pragma unroll
                for (int n = 0; n < 7; n++) {
                    uint32_t lo = bfpk(d2[m][n][1], d2[m][n][0]);
                    uint32_t hi = bfpk(d2[m][n][3], d2[m][n][2]);
                    int noff = (n * 8 + tg * 2) * 2;
                    *(uint32_t*)(grow + pxA * 116 + noff) = lo;
                    *(uint32_t*)(grow + (pxA + 8) * 116 + noff) = hi;
                }
            }
        }

        // advance ring trackers (+8 mod 24)
        rslot += 8; if (rslot >= 24) rslot -= 24;
        gbase += 8; if (gbase >= 24) gbase -= 24;
    }

    __syncthreads();
    float* red = (float*)(smem + RED_OFF);
    #pragma unroll
    for (int o = 16; o > 0; o >>= 1) ss += __shfl_down_sync(0xffffffffu, ss, o);
    if (lane == 0) red[wid] = ss;
    __syncthreads();
    if (tid == 0) {
        float t = 0.f;
        #pragma unroll
        for (int w = 0; w < 16; w++) t += red[w];
        g_partial[img * 20 + rr] = t;
    }
}

// ---------------- K3: scale + out = net_input + r*scale ----------------
__global__ void final_kernel(const float* __restrict__ net_input,
                             const float* __restrict__ stdn,
                             const float* __restrict__ alpha,
                             float* __restrict__ out) {
    __shared__ float sc_sh;
    int v = blockIdx.x * blockDim.x + threadIdx.x;  // float4 index
    int b = v >> 14;
    if (threadIdx.x == 0) {
        float s = 0.f;
        #pragma unroll
        for (int t = 0; t < 20; t++) s += g_partial[b * 20 + t];
        float nr = sqrtf(s);
        float k = expf(alpha[0]) * stdn[b] * 256.f;
        sc_sh = fminf(1.f, k / (nr + 1e-12f));
    }
    __syncthreads();
    float sc = sc_sh;
    float4 rr = ((const float4*)g_r)[v];
    float4 nn = ((const float4*)net_input)[v];
    float4 o;
    o.x = nn.x + rr.x * sc;
    o.y = nn.y + rr.y * sc;
    o.z = nn.z + rr.z * sc;
    o.w = nn.w + rr.w * sc;
    ((float4*)out)[v] = o;
}

extern "C" void kernel_launch(void* const* d_in, const int* in_sizes, int n_in,
                              void* d_out, int out_size) {
    const float* input     = (const float*)d_in[0];
    const float* stdn      = (const float*)d_in[1];
    const float* net_input = (const float*)d_in[3];
    const float* cw        = (const float*)d_in[4];
    const float* sf        = (const float*)d_in[5];
    const float* alpha     = (const float*)d_in[6];
    const float* rbw       = (const float*)d_in[7];
    const float* rbc       = (const float*)d_in[8];
    float* out = (float*)d_out;

    cudaFuncSetAttribute(main_kernel, cudaFuncAttributeMaxDynamicSharedMemorySize, SMEM_TOTAL);

    prep_kernel<<<NF, 256>>>(cw, sf, rbw, rbc);
    pack_kernel<<<1, 768>>>();
    dummy_kernel<<<1, 32>>>();
    main_kernel<<<320, 512, SMEM_TOTAL>>>(input, net_input);
    final_kernel<<<1024, 256>>>(net_input, stdn, alpha, out);
}

// round 14
// speedup vs baseline: 1.0272x; 1.0272x over previous
#include <cuda_runtime.h>
#include <cuda_bf16.h>
#include <math.h>
#include <stdint.h>

#define NF   48
#define NM   51
#define IMG  256
#define TABN 2049

// ---- dynamic smem layout (bytes) ----
#define XSTR    56              // halo stride in halves
#define XCPY    4928            // one shifted x copy: 44 rows * 56 halves * 2B
#define B1P_OFF 9856            // 768 uint2 = 6144
#define B2P_OFF 16000           // 672 uint2 = 5376
#define G_OFF   21376           // ring: 16 * GROWR = 89088
#define GROWR   5568            // 48 px * 116B
#define GPX     116
#define RED_OFF 110464
#define SMEM_TOTAL 110592

// ---- device scratch ----
__device__ __align__(16) __nv_bfloat16 g_B1[NF * 64];   // [f][k=p*8+q]
__device__ __align__(16) __nv_bfloat16 g_B2[64 * 64];   // [n=p*8+q][f] (f>=48 zero)
__device__ __align__(16) uint2 g_B1p[768];              // frag-ordered: (k*6+n)*32+lane
__device__ __align__(16) uint2 g_B2p[672];              // frag-ordered: (k*7+n)*32+lane
__device__ float2 g_tab[NF * TABN];
__device__ float  g_r[16 * IMG * IMG];
__device__ float  g_partial[16 * 56];

__device__ __forceinline__ void mma_bf16(float c[4], const uint32_t a[4],
                                         uint32_t b0, uint32_t b1) {
    asm volatile("mma.sync.aligned.m16n8k16.row.col.f32.bf16.bf16.f32 "
        "{%0,%1,%2,%3}, {%4,%5,%6,%7}, {%8,%9}, {%0,%1,%2,%3};"
        : "+f"(c[0]), "+f"(c[1]), "+f"(c[2]), "+f"(c[3])
        : "r"(a[0]), "r"(a[1]), "r"(a[2]), "r"(a[3]), "r"(b0), "r"(b1));
}
__device__ __forceinline__ uint32_t bfpk(float hi, float lo) {
    uint32_t r; asm("cvt.rn.bf16x2.f32 %0, %1, %2;" : "=r"(r) : "f"(hi), "f"(lo)); return r;
}

// ---------------- K1: normalize weights -> B1/B2 bf16 + RBF tables ----------------
__global__ void prep_kernel(const float* __restrict__ cw, const float* __restrict__ sf,
                            const float* __restrict__ rbw, const float* __restrict__ rbc) {
    __shared__ float wn[49];
    __shared__ float msh[2];
    __shared__ float wsh[NM], csh[NM];
    __shared__ float tsh[TABN];
    int f = blockIdx.x, tid = threadIdx.x;

    if (tid < 49) wn[tid] = cw[f * 49 + tid];
    if (tid < NM) { wsh[tid] = rbw[f * NM + tid]; csh[tid] = rbc[tid]; }
    __syncthreads();
    if (tid == 0) {
        float mean = 0.f;
        #pragma unroll
        for (int i = 0; i < 49; i++) mean += wn[i];
        mean *= (1.f / 49.f);
        float ssq = 0.f;
        #pragma unroll
        for (int i = 0; i < 49; i++) { float d = wn[i] - mean; ssq += d * d; }
        msh[0] = mean;
        msh[1] = sf[f] / (sqrtf(ssq) + 1e-12f);
    }
    __syncthreads();
    if (tid < 49) wn[tid] = (wn[tid] - msh[0]) * msh[1];
    __syncthreads();
    if (tid < 64) {
        int p = tid >> 3, q = tid & 7;
        float v = (p < 7 && q < 7) ? wn[p * 7 + q] : 0.f;
        g_B1[f * 64 + tid] = __float2bfloat16(v);   // [f][k]
        g_B2[tid * 64 + f] = __float2bfloat16(v);   // [n][f]
    }
    for (int k = tid; k < TABN; k += blockDim.x) {
        float z = -16.f + (float)k * (1.f / 64.f);
        float acc = 0.f;
        #pragma unroll
        for (int m = 0; m < NM; m++) {
            float d = z - csh[m];
            acc += wsh[m] * __expf(-0.01f * d * d);
        }
        tsh[k] = acc;
    }
    __syncthreads();
    for (int k = tid; k < TABN; k += blockDim.x) {
        float v = tsh[k];
        float dl = (k < TABN - 1) ? (tsh[k + 1] - v) : 0.f;
        g_tab[f * TABN + k] = make_float2(v, dl);
    }
}

// ---------------- K1b: pack B matrices into mma-fragment order ----------------
__global__ void pack_kernel() {
    int i = threadIdx.x;          // 768 threads
    {
        int lane = i & 31, kn = i >> 5;      // kn < 24
        int k = kn / 6, n = kn - k * 6;
        int g = lane >> 2, tg = lane & 3;
        const uint32_t* row = (const uint32_t*)(g_B1 + (n * 8 + g) * 64);
        uint2 v;
        v.x = row[(k * 16 + tg * 2) >> 1];
        v.y = row[(k * 16 + tg * 2 + 8) >> 1];
        g_B1p[i] = v;
    }
    if (i < 672) {
        int lane = i & 31, kn = i >> 5;      // kn < 21
        int k = kn / 7, n = kn - k * 7;
        int g = lane >> 2, tg = lane & 3;
        const uint32_t* row = (const uint32_t*)(g_B2 + (n * 8 + g) * 64);
        uint2 v;
        v.x = row[(k * 16 + tg * 2) >> 1];
        v.y = row[(k * 16 + tg * 2 + 8) >> 1];
        g_B2p[i] = v;
    }
}

__global__ void dummy_kernel() {}

// ---------------- K2: fused tensor-core main (mma.sync, 2 CTAs/SM) ----------------
// grid 896 = 16 img x 8 ytiles(32) x 7 xtiles(42); 384 threads
__global__ void __launch_bounds__(384, 2)
main_kernel(const float* __restrict__ input, const float* __restrict__ net_input) {
    extern __shared__ __align__(16) char smem[];

    int bid = blockIdx.x;
    int img = bid / 56;
    int rr  = bid % 56;
    int y0 = (rr / 7) * 32;
    int x0 = (rr % 7) * 42;
    int tid  = threadIdx.x;
    int wid  = tid >> 5;
    int lane = tid & 31;

    const float* ibase = input + img * IMG * IMG;
    const float* nbase = net_input + img * IMG * IMG;

    // ---- stage x halo: 2 shifted bf16 copies (44 rows x 55 cols) ----
    __nv_bfloat16* xs0 = (__nv_bfloat16*)smem;
    __nv_bfloat16* xs1 = (__nv_bfloat16*)(smem + XCPY);
    for (int idx = tid; idx < 44 * 55; idx += 384) {
        int xr = idx / 55, xc = idx - xr * 55;
        int gy = y0 - 6 + xr, gx = x0 - 6 + xc;
        gy = (gy < 0) ? (-1 - gy) : ((gy >= IMG) ? (2 * IMG - 1 - gy) : gy);
        gx = (gx < 0) ? (-1 - gx) : ((gx >= IMG) ? (2 * IMG - 1 - gx) : gx);
        __nv_bfloat16 v = __float2bfloat16(ibase[gy * IMG + gx]);
        xs0[xr * XSTR + xc] = v;
        if (xc >= 1) xs1[xr * XSTR + xc - 1] = v;
    }
    // ---- stage packed B fragments ----
    {
        uint2* d1p = (uint2*)(smem + B1P_OFF);
        uint2* d2p = (uint2*)(smem + B2P_OFF);
        for (int i = tid; i < 768; i += 384) d1p[i] = g_B1p[i];
        for (int i = tid; i < 672; i += 384) d2p[i] = g_B2p[i];
    }
    __syncthreads();

    int g  = lane >> 2;       // 0..7
    int tg = lane & 3;        // 0..3
    float ss = 0.f;

    // worker per-m constants: groups j = 2*wid + m; row j/3, colbase (j%3)*16
    int rjm[2], cbm[2], colB[2];
    #pragma unroll
    for (int m = 0; m < 2; m++) {
        int j = 2 * wid + m;
        rjm[m] = j / 3;
        cbm[m] = (j - rjm[m] * 3) * 16;
        colB[m] = cbm[m] + g + 2 * tg - (g & 1);
    }
    const char* xcp = smem + (g & 1) * XCPY;
    const uint2* bp1 = (const uint2*)(smem + B1P_OFF) + lane;
    const uint2* bp2 = (const uint2*)(smem + B2P_OFF) + lane;

    // gather constants
    int xl = tid % 48;
    int yh = tid / 48;                   // 0..7

    #pragma unroll 1
    for (int s = 0; s < 5; s++) {
        __syncthreads();   // prev gather done before ring-slot reuse

        // ---- produce slab s: a-rows 8s..8s+7 ----
        int ram[2];
        bool ok[2];
        int ramc[2];
        #pragma unroll
        for (int m = 0; m < 2; m++) {
            ram[m]  = 8 * s + rjm[m];
            ok[m]   = ram[m] < 38;
            ramc[m] = ok[m] ? ram[m] : 0;
        }

        // GEMM1: D1[16px x 48f] per m, A frags direct from x copies
        float d1[2][6][4];
        #pragma unroll
        for (int m = 0; m < 2; m++)
            #pragma unroll
            for (int n = 0; n < 6; n++)
                #pragma unroll
                for (int e = 0; e < 4; e++) d1[m][n][e] = 0.f;
        #pragma unroll
        for (int k = 0; k < 4; k++) {
            uint32_t afr[2][4];
            #pragma unroll
            for (int m = 0; m < 2; m++) {
                const char* ab = xcp + (((ramc[m] + 2 * k) * XSTR) + colB[m]) * 2;
                afr[m][0] = *(const uint32_t*)ab;
                afr[m][1] = *(const uint32_t*)(ab + 16);
                if (k < 3) {
                    afr[m][2] = *(const uint32_t*)(ab + 2 * XSTR);
                    afr[m][3] = *(const uint32_t*)(ab + 2 * XSTR + 16);
                } else {
                    afr[m][2] = 0u; afr[m][3] = 0u;   // k>=56 hits zero B cols
                }
            }
            #pragma unroll
            for (int n = 0; n < 6; n++) {
                uint2 b01 = bp1[(k * 6 + n) * 32];
                mma_bf16(d1[0][n], afr[0], b01.x, b01.y);
                mma_bf16(d1[1][n], afr[1], b01.x, b01.y);
            }
        }

        // RBF lerp in-register via global table (+ zero outside image)
        #pragma unroll
        for (int m = 0; m < 2; m++) {
            int u = y0 - 3 + ram[m];
            bool uok = (u >= 0) && (u < IMG);
            int vA = x0 - 3 + cbm[m] + g;
            int vB = vA + 8;
            bool okA = uok && (vA >= 0) && (vA < IMG);
            bool okB = uok && (vB >= 0) && (vB < IMG);
            #pragma unroll
            for (int n = 0; n < 6; n++) {
                #pragma unroll
                for (int e = 0; e < 4; e++) {
                    bool okp = (e < 2) ? okA : okB;
                    int fidx = n * 8 + tg * 2 + (e & 1);
                    float z = d1[m][n][e];
                    float t = fminf(fmaxf((z + 16.f) * 64.f, 0.f), 2047.99f);
                    int ix = (int)t;
                    float fr = t - (float)ix;
                    float2 tv = __ldg(&g_tab[fidx * TABN + ix]);
                    float a = tv.x + fr * tv.y;
                    d1[m][n][e] = okp ? a : 0.f;
                }
            }
        }

        // repack D1 -> A fragments of GEMM2 (register-only)
        uint32_t a2[2][3][4];
        #pragma unroll
        for (int m = 0; m < 2; m++)
            #pragma unroll
            for (int t = 0; t < 3; t++) {
                a2[m][t][0] = bfpk(d1[m][2 * t][1],     d1[m][2 * t][0]);
                a2[m][t][1] = bfpk(d1[m][2 * t][3],     d1[m][2 * t][2]);
                a2[m][t][2] = bfpk(d1[m][2 * t + 1][1], d1[m][2 * t + 1][0]);
                a2[m][t][3] = bfpk(d1[m][2 * t + 1][3], d1[m][2 * t + 1][2]);
            }

        char* grow[2];
        #pragma unroll
        for (int m = 0; m < 2; m++)
            grow[m] = smem + G_OFF + (ram[m] & 15) * GROWR;

        // GEMM2 half 1: n = 0..3
        {
            float d2[2][4][4];
            #pragma unroll
            for (int m = 0; m < 2; m++)
                #pragma unroll
                for (int n = 0; n < 4; n++)
                    #pragma unroll
                    for (int e = 0; e < 4; e++) d2[m][n][e] = 0.f;
            #pragma unroll
            for (int k = 0; k < 3; k++) {
                #pragma unroll
                for (int n = 0; n < 4; n++) {
                    uint2 b01 = bp2[(k * 7 + n) * 32];
                    mma_bf16(d2[0][n], a2[0][k], b01.x, b01.y);
                    mma_bf16(d2[1][n], a2[1][k], b01.x, b01.y);
                }
            }
            #pragma unroll
            for (int m = 0; m < 2; m++) {
                if (ok[m]) {
                    int pxA = cbm[m] + g;
                    #pragma unroll
                    for (int n = 0; n < 4; n++) {
                        uint32_t lo = bfpk(d2[m][n][1], d2[m][n][0]);
                        uint32_t hi = bfpk(d2[m][n][3], d2[m][n][2]);
                        int noff = (n * 8 + tg * 2) * 2;
                        *(uint32_t*)(grow[m] + pxA * GPX + noff) = lo;
                        *(uint32_t*)(grow[m] + (pxA + 8) * GPX + noff) = hi;
                    }
                }
            }
        }
        // GEMM2 half 2: n = 4..6
        {
            float d2[2][3][4];
            #pragma unroll
            for (int m = 0; m < 2; m++)
                #pragma unroll
                for (int n = 0; n < 3; n++)
                    #pragma unroll
                    for (int e = 0; e < 4; e++) d2[m][n][e] = 0.f;
            #pragma unroll
            for (int k = 0; k < 3; k++) {
                #pragma unroll
                for (int n = 0; n < 3; n++) {
                    uint2 b01 = bp2[(k * 7 + n + 4) * 32];
                    mma_bf16(d2[0][n], a2[0][k], b01.x, b01.y);
                    mma_bf16(d2[1][n], a2[1][k], b01.x, b01.y);
                }
            }
            #pragma unroll
            for (int m = 0; m < 2; m++) {
                if (ok[m]) {
                    int pxA = cbm[m] + g;
                    #pragma unroll
                    for (int n = 0; n < 3; n++) {
                        uint32_t lo = bfpk(d2[m][n][1], d2[m][n][0]);
                        uint32_t hi = bfpk(d2[m][n][3], d2[m][n][2]);
                        int noff = ((n + 4) * 8 + tg * 2) * 2;
                        *(uint32_t*)(grow[m] + pxA * GPX + noff) = lo;
                        *(uint32_t*)(grow[m] + (pxA + 8) * GPX + noff) = hi;
                    }
                }
            }
        }

        __syncthreads();   // G for slab s complete

        // ---- gather: col2im + residual for out rows 8(s-1)..8(s-1)+7 ----
        if (s >= 1) {
            int yl = 8 * (s - 1) + yh;
            int xg = x0 + xl;
            if (xl < 42 && xg < IMG) {
                float cv = 0.f;
                #pragma unroll
                for (int p = 0; p < 7; p++) {
                    const char* rb = smem + G_OFF + ((yl + 6 - p) & 15) * GROWR + p * 16;
                    #pragma unroll
                    for (int q = 0; q < 7; q++) {
                        uint16_t gv = *(const uint16_t*)(rb + (xl + 6 - q) * GPX + q * 2);
                        cv += __uint_as_float((uint32_t)gv << 16);
                    }
                }
                int yg = y0 + yl;
                float iv = ibase[yg * IMG + xg];
                float nv = nbase[yg * IMG + xg];
                float rv = iv - cv - nv;
                g_r[img * IMG * IMG + yg * IMG + xg] = rv;
                ss += rv * rv;
            }
        }
    }

    __syncthreads();
    float* red = (float*)(smem + RED_OFF);
    #pragma unroll
    for (int o = 16; o > 0; o >>= 1) ss += __shfl_down_sync(0xffffffffu, ss, o);
    if (lane == 0) red[wid] = ss;
    __syncthreads();
    if (tid == 0) {
        float t = 0.f;
        #pragma unroll
        for (int w = 0; w < 12; w++) t += red[w];
        g_partial[img * 56 + rr] = t;
    }
}

// ---------------- K3: scale + out = net_input + r*scale ----------------
__global__ void final_kernel(const float* __restrict__ net_input,
                             const float* __restrict__ stdn,
                             const float* __restrict__ alpha,
                             float* __restrict__ out) {
    __shared__ float sc_sh;
    int v = blockIdx.x * blockDim.x + threadIdx.x;  // float4 index
    int b = v >> 14;
    if (threadIdx.x == 0) {
        float s = 0.f;
        #pragma unroll
        for (int t = 0; t < 56; t++) s += g_partial[b * 56 + t];
        float nr = sqrtf(s);
        float k = expf(alpha[0]) * stdn[b] * 256.f;
        sc_sh = fminf(1.f, k / (nr + 1e-12f));
    }
    __syncthreads();
    float sc = sc_sh;
    float4 rr = ((const float4*)g_r)[v];
    float4 nn = ((const float4*)net_input)[v];
    float4 o;
    o.x = nn.x + rr.x * sc;
    o.y = nn.y + rr.y * sc;
    o.z = nn.z + rr.z * sc;
    o.w = nn.w + rr.w * sc;
    ((float4*)out)[v] = o;
}

extern "C" void kernel_launch(void* const* d_in, const int* in_sizes, int n_in,
                              void* d_out, int out_size) {
    const float* input     = (const float*)d_in[0];
    const float* stdn      = (const float*)d_in[1];
    const float* net_input = (const float*)d_in[3];
    const float* cw        = (const float*)d_in[4];
    const float* sf        = (const float*)d_in[5];
    const float* alpha     = (const float*)d_in[6];
    const float* rbw       = (const float*)d_in[7];
    const float* rbc       = (const float*)d_in[8];
    float* out = (float*)d_out;

    cudaFuncSetAttribute(main_kernel, cudaFuncAttributeMaxDynamicSharedMemorySize, SMEM_TOTAL);

    prep_kernel<<<NF, 256>>>(cw, sf, rbw, rbc);
    pack_kernel<<<1, 768>>>();
    dummy_kernel<<<1, 32>>>();
    main_kernel<<<896, 384, SMEM_TOTAL>>>(input, net_input);
    final_kernel<<<1024, 256>>>(net_input, stdn, alpha, out);
}

// round 15
// speedup vs baseline: 1.2172x; 1.1850x over previous
#include <cuda_runtime.h>
#include <cuda_bf16.h>
#include <math.h>
#include <stdint.h>

#define NF   48
#define NM   51
#define IMG  256
#define TABN 1025

// ---- dynamic smem layout (bytes) ----
#define XSTR    56              // halo stride in halves
#define XCPY    4928            // one shifted x copy: 44 rows * 56 halves * 2B
#define B1P_OFF 9856            // 768 uint2 = 6144
#define B2P_OFF 16000           // 672 uint2 = 5376
#define G_OFF   21376           // ring: 16 * GROWR = 89088
#define GROWR   5568            // 48 px * 116B
#define GPX     116
#define RED_OFF 110464
#define SMEM_TOTAL 110592

// ---- device scratch ----
__device__ __align__(16) __nv_bfloat16 g_B1[NF * 64];   // [f][k=p*8+q]
__device__ __align__(16) __nv_bfloat16 g_B2[64 * 64];   // [n=p*8+q][f] (f>=48 zero)
__device__ __align__(16) uint2 g_B1p[768];              // frag-ordered: (k*6+n)*32+lane
__device__ __align__(16) uint2 g_B2p[672];              // frag-ordered: (k*7+n)*32+lane
__device__ __align__(16) uint32_t g_tabp[NF * TABN];    // packed bf16 (value | delta<<16)
__device__ float  g_r[16 * IMG * IMG];
__device__ float  g_partial[16 * 56];

__device__ __forceinline__ void mma_bf16(float c[4], const uint32_t a[4],
                                         uint32_t b0, uint32_t b1) {
    asm volatile("mma.sync.aligned.m16n8k16.row.col.f32.bf16.bf16.f32 "
        "{%0,%1,%2,%3}, {%4,%5,%6,%7}, {%8,%9}, {%0,%1,%2,%3};"
        : "+f"(c[0]), "+f"(c[1]), "+f"(c[2]), "+f"(c[3])
        : "r"(a[0]), "r"(a[1]), "r"(a[2]), "r"(a[3]), "r"(b0), "r"(b1));
}
__device__ __forceinline__ uint32_t bfpk(float hi, float lo) {
    uint32_t r; asm("cvt.rn.bf16x2.f32 %0, %1, %2;" : "=r"(r) : "f"(hi), "f"(lo)); return r;
}

// ---------------- K1: normalize weights -> B1/B2 bf16 + packed RBF tables ----------------
__global__ void prep_kernel(const float* __restrict__ cw, const float* __restrict__ sf,
                            const float* __restrict__ rbw, const float* __restrict__ rbc) {
    __shared__ float wn[49];
    __shared__ float msh[2];
    __shared__ float wsh[NM], csh[NM];
    __shared__ float tsh[TABN];
    int f = blockIdx.x, tid = threadIdx.x;

    if (tid < 49) wn[tid] = cw[f * 49 + tid];
    if (tid < NM) { wsh[tid] = rbw[f * NM + tid]; csh[tid] = rbc[tid]; }
    __syncthreads();
    if (tid == 0) {
        float mean = 0.f;
        #pragma unroll
        for (int i = 0; i < 49; i++) mean += wn[i];
        mean *= (1.f / 49.f);
        float ssq = 0.f;
        #pragma unroll
        for (int i = 0; i < 49; i++) { float d = wn[i] - mean; ssq += d * d; }
        msh[0] = mean;
        msh[1] = sf[f] / (sqrtf(ssq) + 1e-12f);
    }
    __syncthreads();
    if (tid < 49) wn[tid] = (wn[tid] - msh[0]) * msh[1];
    __syncthreads();
    if (tid < 64) {
        int p = tid >> 3, q = tid & 7;
        float v = (p < 7 && q < 7) ? wn[p * 7 + q] : 0.f;
        g_B1[f * 64 + tid] = __float2bfloat16(v);   // [f][k]
        g_B2[tid * 64 + f] = __float2bfloat16(v);   // [n][f]
    }
    for (int k = tid; k < TABN; k += blockDim.x) {
        float z = -8.f + (float)k * (1.f / 64.f);
        float acc = 0.f;
        #pragma unroll
        for (int m = 0; m < NM; m++) {
            float d = z - csh[m];
            acc += wsh[m] * __expf(-0.01f * d * d);
        }
        tsh[k] = acc;
    }
    __syncthreads();
    for (int k = tid; k < TABN; k += blockDim.x) {
        float v = tsh[k];
        float dl = (k < TABN - 1) ? (tsh[k + 1] - v) : 0.f;
        g_tabp[f * TABN + k] = bfpk(dl, v);   // low=value, high=delta
    }
}

// ---------------- K1b: pack B matrices into mma-fragment order ----------------
__global__ void pack_kernel() {
    int i = threadIdx.x;          // 768 threads
    {
        int lane = i & 31, kn = i >> 5;      // kn < 24
        int k = kn / 6, n = kn - k * 6;
        int g = lane >> 2, tg = lane & 3;
        const uint32_t* row = (const uint32_t*)(g_B1 + (n * 8 + g) * 64);
        uint2 v;
        v.x = row[(k * 16 + tg * 2) >> 1];
        v.y = row[(k * 16 + tg * 2 + 8) >> 1];
        g_B1p[i] = v;
    }
    if (i < 672) {
        int lane = i & 31, kn = i >> 5;      // kn < 21
        int k = kn / 7, n = kn - k * 7;
        int g = lane >> 2, tg = lane & 3;
        const uint32_t* row = (const uint32_t*)(g_B2 + (n * 8 + g) * 64);
        uint2 v;
        v.x = row[(k * 16 + tg * 2) >> 1];
        v.y = row[(k * 16 + tg * 2 + 8) >> 1];
        g_B2p[i] = v;
    }
}

__global__ void dummy_kernel() {}

// ---------------- K2: fused tensor-core main (mma.sync, 2 CTAs/SM) ----------------
// grid 896 = 16 img x 8 ytiles(32) x 7 xtiles(42); 384 threads
__global__ void __launch_bounds__(384, 2)
main_kernel(const float* __restrict__ input, const float* __restrict__ net_input) {
    extern __shared__ __align__(16) char smem[];

    int bid = blockIdx.x;
    int img = bid / 56;
    int rr  = bid % 56;
    int y0 = (rr / 7) * 32;
    int x0 = (rr % 7) * 42;
    int tid  = threadIdx.x;
    int wid  = tid >> 5;
    int lane = tid & 31;

    const float* ibase = input + img * IMG * IMG;
    const float* nbase = net_input + img * IMG * IMG;

    // ---- stage x halo: 2 shifted bf16 copies (44 rows x 55 cols) ----
    __nv_bfloat16* xs0 = (__nv_bfloat16*)smem;
    __nv_bfloat16* xs1 = (__nv_bfloat16*)(smem + XCPY);
    for (int idx = tid; idx < 44 * 55; idx += 384) {
        int xr = idx / 55, xc = idx - xr * 55;
        int gy = y0 - 6 + xr, gx = x0 - 6 + xc;
        gy = (gy < 0) ? (-1 - gy) : ((gy >= IMG) ? (2 * IMG - 1 - gy) : gy);
        gx = (gx < 0) ? (-1 - gx) : ((gx >= IMG) ? (2 * IMG - 1 - gx) : gx);
        __nv_bfloat16 v = __float2bfloat16(ibase[gy * IMG + gx]);
        xs0[xr * XSTR + xc] = v;
        if (xc >= 1) xs1[xr * XSTR + xc - 1] = v;
    }
    // ---- stage packed B fragments ----
    {
        uint2* d1p = (uint2*)(smem + B1P_OFF);
        uint2* d2p = (uint2*)(smem + B2P_OFF);
        for (int i = tid; i < 768; i += 384) d1p[i] = g_B1p[i];
        for (int i = tid; i < 672; i += 384) d2p[i] = g_B2p[i];
    }
    __syncthreads();

    int g  = lane >> 2;       // 0..7
    int tg = lane & 3;        // 0..3
    float ss = 0.f;

    // worker per-m constants: groups j = 2*wid + m; row j/3, colbase (j%3)*16
    int rjm[2], cbm[2], colB[2];
    #pragma unroll
    for (int m = 0; m < 2; m++) {
        int j = 2 * wid + m;
        rjm[m] = j / 3;
        cbm[m] = (j - rjm[m] * 3) * 16;
        colB[m] = cbm[m] + g + 2 * tg - (g & 1);
    }
    const char* xcp = smem + (g & 1) * XCPY;
    const uint2* bp1 = (const uint2*)(smem + B1P_OFF) + lane;
    const uint2* bp2 = (const uint2*)(smem + B2P_OFF) + lane;

    // gather constants
    int xl = tid % 48;
    int yh = tid / 48;                   // 0..7

    #pragma unroll 1
    for (int s = 0; s < 5; s++) {
        __syncthreads();   // prev gather done before ring-slot reuse

        // ---- produce slab s: a-rows 8s..8s+7 ----
        int ram[2];
        bool ok[2];
        int ramc[2];
        #pragma unroll
        for (int m = 0; m < 2; m++) {
            ram[m]  = 8 * s + rjm[m];
            ok[m]   = ram[m] < 38;
            ramc[m] = ok[m] ? ram[m] : 0;
        }

        // GEMM1: D1[16px x 48f] per m, A frags direct from x copies
        float d1[2][6][4];
        #pragma unroll
        for (int m = 0; m < 2; m++)
            #pragma unroll
            for (int n = 0; n < 6; n++)
                #pragma unroll
                for (int e = 0; e < 4; e++) d1[m][n][e] = 0.f;
        #pragma unroll
        for (int k = 0; k < 4; k++) {
            uint32_t afr[2][4];
            #pragma unroll
            for (int m = 0; m < 2; m++) {
                const char* ab = xcp + (((ramc[m] + 2 * k) * XSTR) + colB[m]) * 2;
                afr[m][0] = *(const uint32_t*)ab;
                afr[m][1] = *(const uint32_t*)(ab + 16);
                if (k < 3) {
                    afr[m][2] = *(const uint32_t*)(ab + 2 * XSTR);
                    afr[m][3] = *(const uint32_t*)(ab + 2 * XSTR + 16);
                } else {
                    afr[m][2] = 0u; afr[m][3] = 0u;   // k>=56 hits zero B cols
                }
            }
            #pragma unroll
            for (int n = 0; n < 6; n++) {
                uint2 b01 = bp1[(k * 6 + n) * 32];
                mma_bf16(d1[0][n], afr[0], b01.x, b01.y);
                mma_bf16(d1[1][n], afr[1], b01.x, b01.y);
            }
        }

        // RBF lerp via packed u32 table (+ zero outside image)
        #pragma unroll
        for (int m = 0; m < 2; m++) {
            int u = y0 - 3 + ram[m];
            bool uok = (u >= 0) && (u < IMG);
            int vA = x0 - 3 + cbm[m] + g;
            int vB = vA + 8;
            bool okA = uok && (vA >= 0) && (vA < IMG);
            bool okB = uok && (vB >= 0) && (vB < IMG);
            #pragma unroll
            for (int n = 0; n < 6; n++) {
                #pragma unroll
                for (int e = 0; e < 4; e++) {
                    bool okp = (e < 2) ? okA : okB;
                    int fidx = n * 8 + tg * 2 + (e & 1);
                    float z = d1[m][n][e];
                    float t = fminf(fmaxf((z + 8.f) * 64.f, 0.f), 1023.99f);
                    int ix = (int)t;
                    float fr = t - (float)ix;
                    uint32_t tv = __ldg(&g_tabp[fidx * TABN + ix]);
                    float val = __uint_as_float(tv << 16);
                    float dlt = __uint_as_float(tv & 0xffff0000u);
                    float a = fmaf(fr, dlt, val);
                    d1[m][n][e] = okp ? a : 0.f;
                }
            }
        }

        // repack D1 -> A fragments of GEMM2 (register-only)
        uint32_t a2[2][3][4];
        #pragma unroll
        for (int m = 0; m < 2; m++)
            #pragma unroll
            for (int t = 0; t < 3; t++) {
                a2[m][t][0] = bfpk(d1[m][2 * t][1],     d1[m][2 * t][0]);
                a2[m][t][1] = bfpk(d1[m][2 * t][3],     d1[m][2 * t][2]);
                a2[m][t][2] = bfpk(d1[m][2 * t + 1][1], d1[m][2 * t + 1][0]);
                a2[m][t][3] = bfpk(d1[m][2 * t + 1][3], d1[m][2 * t + 1][2]);
            }

        char* grow[2];
        #pragma unroll
        for (int m = 0; m < 2; m++)
            grow[m] = smem + G_OFF + (ram[m] & 15) * GROWR;

        // GEMM2 half 1: n = 0..3
        {
            float d2[2][4][4];
            #pragma unroll
            for (int m = 0; m < 2; m++)
                #pragma unroll
                for (int n = 0; n < 4; n++)
                    #pragma unroll
                    for (int e = 0; e < 4; e++) d2[m][n][e] = 0.f;
            #pragma unroll
            for (int k = 0; k < 3; k++) {
                #pragma unroll
                for (int n = 0; n < 4; n++) {
                    uint2 b01 = bp2[(k * 7 + n) * 32];
                    mma_bf16(d2[0][n], a2[0][k], b01.x, b01.y);
                    mma_bf16(d2[1][n], a2[1][k], b01.x, b01.y);
                }
            }
            #pragma unroll
            for (int m = 0; m < 2; m++) {
                if (ok[m]) {
                    int pxA = cbm[m] + g;
                    #pragma unroll
                    for (int n = 0; n < 4; n++) {
                        uint32_t lo = bfpk(d2[m][n][1], d2[m][n][0]);
                        uint32_t hi = bfpk(d2[m][n][3], d2[m][n][2]);
                        int noff = (n * 8 + tg * 2) * 2;
                        *(uint32_t*)(grow[m] + pxA * GPX + noff) = lo;
                        *(uint32_t*)(grow[m] + (pxA + 8) * GPX + noff) = hi;
                    }
                }
            }
        }
        // GEMM2 half 2: n = 4..6
        {
            float d2[2][3][4];
            #pragma unroll
            for (int m = 0; m < 2; m++)
                #pragma unroll
                for (int n = 0; n < 3; n++)
                    #pragma unroll
                    for (int e = 0; e < 4; e++) d2[m][n][e] = 0.f;
            #pragma unroll
            for (int k = 0; k < 3; k++) {
                #pragma unroll
                for (int n = 0; n < 3; n++) {
                    uint2 b01 = bp2[(k * 7 + n + 4) * 32];
                    mma_bf16(d2[0][n], a2[0][k], b01.x, b01.y);
                    mma_bf16(d2[1][n], a2[1][k], b01.x, b01.y);
                }
            }
            #pragma unroll
            for (int m = 0; m < 2; m++) {
                if (ok[m]) {
                    int pxA = cbm[m] + g;
                    #pragma unroll
                    for (int n = 0; n < 3; n++) {
                        uint32_t lo = bfpk(d2[m][n][1], d2[m][n][0]);
                        uint32_t hi = bfpk(d2[m][n][3], d2[m][n][2]);
                        int noff = ((n + 4) * 8 + tg * 2) * 2;
                        *(uint32_t*)(grow[m] + pxA * GPX + noff) = lo;
                        *(uint32_t*)(grow[m] + (pxA + 8) * GPX + noff) = hi;
                    }
                }
            }
        }

        __syncthreads();   // G for slab s complete

        // ---- gather: col2im + residual for out rows 8(s-1)..8(s-1)+7 ----
        if (s >= 1) {
            int yl = 8 * (s - 1) + yh;
            int xg = x0 + xl;
            if (xl < 42 && xg < IMG) {
                float cv = 0.f;
                #pragma unroll
                for (int p = 0; p < 7; p++) {
                    const char* rb = smem + G_OFF + ((yl + 6 - p) & 15) * GROWR + p * 16;
                    #pragma unroll
                    for (int q = 0; q < 7; q++) {
                        uint16_t gv = *(const uint16_t*)(rb + (xl + 6 - q) * GPX + q * 2);
                        cv += __uint_as_float((uint32_t)gv << 16);
                    }
                }
                int yg = y0 + yl;
                float iv = ibase[yg * IMG + xg];
                float nv = nbase[yg * IMG + xg];
                float rv = iv - cv - nv;
                g_r[img * IMG * IMG + yg * IMG + xg] = rv;
                ss += rv * rv;
            }
        }
    }

    __syncthreads();
    float* red = (float*)(smem + RED_OFF);
    #pragma unroll
    for (int o = 16; o > 0; o >>= 1) ss += __shfl_down_sync(0xffffffffu, ss, o);
    if (lane == 0) red[wid] = ss;
    __syncthreads();
    if (tid == 0) {
        float t = 0.f;
        #pragma unroll
        for (int w = 0; w < 12; w++) t += red[w];
        g_partial[img * 56 + rr] = t;
    }
}

// ---------------- K3: scale + out = net_input + r*scale ----------------
__global__ void final_kernel(const float* __restrict__ net_input,
                             const float* __restrict__ stdn,
                             const float* __restrict__ alpha,
                             float* __restrict__ out) {
    __shared__ float sc_sh;
    int v = blockIdx.x * blockDim.x + threadIdx.x;  // float4 index
    int b = v >> 14;
    if (threadIdx.x == 0) {
        float s = 0.f;
        #pragma unroll
        for (int t = 0; t < 56; t++) s += g_partial[b * 56 + t];
        float nr = sqrtf(s);
        float k = expf(alpha[0]) * stdn[b] * 256.f;
        sc_sh = fminf(1.f, k / (nr + 1e-12f));
    }
    __syncthreads();
    float sc = sc_sh;
    float4 rr = ((const float4*)g_r)[v];
    float4 nn = ((const float4*)net_input)[v];
    float4 o;
    o.x = nn.x + rr.x * sc;
    o.y = nn.y + rr.y * sc;
    o.z = nn.z + rr.z * sc;
    o.w = nn.w + rr.w * sc;
    ((float4*)out)[v] = o;
}

extern "C" void kernel_launch(void* const* d_in, const int* in_sizes, int n_in,
                              void* d_out, int out_size) {
    const float* input     = (const float*)d_in[0];
    const float* stdn      = (const float*)d_in[1];
    const float* net_input = (const float*)d_in[3];
    const float* cw        = (const float*)d_in[4];
    const float* sf        = (const float*)d_in[5];
    const float* alpha     = (const float*)d_in[6];
    const float* rbw       = (const float*)d_in[7];
    const float* rbc       = (const float*)d_in[8];
    float* out = (float*)d_out;

    cudaFuncSetAttribute(main_kernel, cudaFuncAttributeMaxDynamicSharedMemorySize, SMEM_TOTAL);

    prep_kernel<<<NF, 256>>>(cw, sf, rbw, rbc);
    pack_kernel<<<1, 768>>>();
    dummy_kernel<<<1, 32>>>();
    main_kernel<<<896, 384, SMEM_TOTAL>>>(input, net_input);
    final_kernel<<<1024, 256>>>(net_input, stdn, alpha, out);
}

// round 16
// speedup vs baseline: 1.3095x; 1.0758x over previous
#include <cuda_runtime.h>
#include <cuda_bf16.h>
#include <math.h>
#include <stdint.h>

#define NF   48
#define NM   51
#define IMG  256
#define TABN 1025

// ---- dynamic smem layout (bytes) ----
#define XSTR    56              // halo stride in halves
#define XCPY    4928            // one shifted x copy: 44 rows * 56 halves * 2B
#define B1P_OFF 9856            // 768 uint2 = 6144
#define B2P_OFF 16000           // 672 uint2 = 5376
#define G_OFF   21376           // ring: 16 * GROWR = 89088
#define GROWR   5568            // 48 px * 116B
#define GPX     116
#define RED_OFF 110464
#define SMEM_TOTAL 110592

// ---- device scratch ----
__device__ __align__(16) __nv_bfloat16 g_B1[NF * 64];   // [f][k=p*8+q]
__device__ __align__(16) __nv_bfloat16 g_B2[64 * 64];   // [n=p*8+q][f] (f>=48 zero)
__device__ __align__(16) uint2 g_B1p[768];              // frag-ordered: (k*6+n)*32+lane
__device__ __align__(16) uint2 g_B2p[672];              // frag-ordered: (k*7+n)*32+lane
__device__ __align__(16) uint16_t g_tabn[NF * TABN];    // bf16 value, nearest-neighbor table
__device__ float  g_r[16 * IMG * IMG];
__device__ float  g_partial[16 * 56];

__device__ __forceinline__ void mma_bf16(float c[4], const uint32_t a[4],
                                         uint32_t b0, uint32_t b1) {
    asm volatile("mma.sync.aligned.m16n8k16.row.col.f32.bf16.bf16.f32 "
        "{%0,%1,%2,%3}, {%4,%5,%6,%7}, {%8,%9}, {%0,%1,%2,%3};"
        : "+f"(c[0]), "+f"(c[1]), "+f"(c[2]), "+f"(c[3])
        : "r"(a[0]), "r"(a[1]), "r"(a[2]), "r"(a[3]), "r"(b0), "r"(b1));
}
__device__ __forceinline__ uint32_t bfpk(float hi, float lo) {
    uint32_t r; asm("cvt.rn.bf16x2.f32 %0, %1, %2;" : "=r"(r) : "f"(hi), "f"(lo)); return r;
}

// ---------------- K1: normalize weights -> B1/B2 bf16 + NN RBF table ----------------
__global__ void prep_kernel(const float* __restrict__ cw, const float* __restrict__ sf,
                            const float* __restrict__ rbw, const float* __restrict__ rbc) {
    __shared__ float wn[49];
    __shared__ float msh[2];
    __shared__ float wsh[NM], csh[NM];
    int f = blockIdx.x, tid = threadIdx.x;

    if (tid < 49) wn[tid] = cw[f * 49 + tid];
    if (tid < NM) { wsh[tid] = rbw[f * NM + tid]; csh[tid] = rbc[tid]; }
    __syncthreads();
    if (tid == 0) {
        float mean = 0.f;
        #pragma unroll
        for (int i = 0; i < 49; i++) mean += wn[i];
        mean *= (1.f / 49.f);
        float ssq = 0.f;
        #pragma unroll
        for (int i = 0; i < 49; i++) { float d = wn[i] - mean; ssq += d * d; }
        msh[0] = mean;
        msh[1] = sf[f] / (sqrtf(ssq) + 1e-12f);
    }
    __syncthreads();
    if (tid < 49) wn[tid] = (wn[tid] - msh[0]) * msh[1];
    __syncthreads();
    if (tid < 64) {
        int p = tid >> 3, q = tid & 7;
        float v = (p < 7 && q < 7) ? wn[p * 7 + q] : 0.f;
        g_B1[f * 64 + tid] = __float2bfloat16(v);   // [f][k]
        g_B2[tid * 64 + f] = __float2bfloat16(v);   // [n][f]
    }
    for (int k = tid; k < TABN; k += blockDim.x) {
        float z = -8.f + (float)k * (1.f / 64.f);
        float acc = 0.f;
        #pragma unroll
        for (int m = 0; m < NM; m++) {
            float d = z - csh[m];
            acc += wsh[m] * __expf(-0.01f * d * d);
        }
        g_tabn[f * TABN + k] = (uint16_t)(bfpk(0.f, acc) & 0xffffu);
    }
}

// ---------------- K1b: pack B matrices into mma-fragment order ----------------
__global__ void pack_kernel() {
    int i = threadIdx.x;          // 768 threads
    {
        int lane = i & 31, kn = i >> 5;      // kn < 24
        int k = kn / 6, n = kn - k * 6;
        int g = lane >> 2, tg = lane & 3;
        const uint32_t* row = (const uint32_t*)(g_B1 + (n * 8 + g) * 64);
        uint2 v;
        v.x = row[(k * 16 + tg * 2) >> 1];
        v.y = row[(k * 16 + tg * 2 + 8) >> 1];
        g_B1p[i] = v;
    }
    if (i < 672) {
        int lane = i & 31, kn = i >> 5;      // kn < 21
        int k = kn / 7, n = kn - k * 7;
        int g = lane >> 2, tg = lane & 3;
        const uint32_t* row = (const uint32_t*)(g_B2 + (n * 8 + g) * 64);
        uint2 v;
        v.x = row[(k * 16 + tg * 2) >> 1];
        v.y = row[(k * 16 + tg * 2 + 8) >> 1];
        g_B2p[i] = v;
    }
}

__global__ void dummy_kernel() {}

// ---------------- K2: fused tensor-core main (mma.sync, 2 CTAs/SM) ----------------
// grid 896 = 16 img x 8 ytiles(32) x 7 xtiles(42); 384 threads
__global__ void __launch_bounds__(384, 2)
main_kernel(const float* __restrict__ input, const float* __restrict__ net_input) {
    extern __shared__ __align__(16) char smem[];

    int bid = blockIdx.x;
    int img = bid / 56;
    int rr  = bid % 56;
    int y0 = (rr / 7) * 32;
    int x0 = (rr % 7) * 42;
    int tid  = threadIdx.x;
    int wid  = tid >> 5;
    int lane = tid & 31;

    const float* ibase = input + img * IMG * IMG;
    const float* nbase = net_input + img * IMG * IMG;

    // ---- stage x halo: 2 shifted bf16 copies (44 rows x 55 cols) ----
    __nv_bfloat16* xs0 = (__nv_bfloat16*)smem;
    __nv_bfloat16* xs1 = (__nv_bfloat16*)(smem + XCPY);
    for (int idx = tid; idx < 44 * 55; idx += 384) {
        int xr = idx / 55, xc = idx - xr * 55;
        int gy = y0 - 6 + xr, gx = x0 - 6 + xc;
        gy = (gy < 0) ? (-1 - gy) : ((gy >= IMG) ? (2 * IMG - 1 - gy) : gy);
        gx = (gx < 0) ? (-1 - gx) : ((gx >= IMG) ? (2 * IMG - 1 - gx) : gx);
        __nv_bfloat16 v = __float2bfloat16(ibase[gy * IMG + gx]);
        xs0[xr * XSTR + xc] = v;
        if (xc >= 1) xs1[xr * XSTR + xc - 1] = v;
    }
    // ---- stage packed B fragments ----
    {
        uint2* d1p = (uint2*)(smem + B1P_OFF);
        uint2* d2p = (uint2*)(smem + B2P_OFF);
        for (int i = tid; i < 768; i += 384) d1p[i] = g_B1p[i];
        for (int i = tid; i < 672; i += 384) d2p[i] = g_B2p[i];
    }
    __syncthreads();

    int g  = lane >> 2;       // 0..7
    int tg = lane & 3;        // 0..3
    float ss = 0.f;

    // worker per-m constants: groups j = 2*wid + m; row j/3, colbase (j%3)*16
    int rjm[2], cbm[2], colB[2];
    #pragma unroll
    for (int m = 0; m < 2; m++) {
        int j = 2 * wid + m;
        rjm[m] = j / 3;
        cbm[m] = (j - rjm[m] * 3) * 16;
        colB[m] = cbm[m] + g + 2 * tg - (g & 1);
    }
    const char* xcp = smem + (g & 1) * XCPY;
    const uint2* bp1 = (const uint2*)(smem + B1P_OFF) + lane;
    const uint2* bp2 = (const uint2*)(smem + B2P_OFF) + lane;

    // gather constants
    int xl = tid % 48;
    int yh = tid / 48;                   // 0..7

    #pragma unroll 1
    for (int s = 0; s < 5; s++) {
        __syncthreads();   // prev gather done before ring-slot reuse

        // ---- produce slab s: a-rows 8s..8s+7 ----
        int ram[2];
        bool ok[2];
        int ramc[2];
        #pragma unroll
        for (int m = 0; m < 2; m++) {
            ram[m]  = 8 * s + rjm[m];
            ok[m]   = ram[m] < 38;
            ramc[m] = ok[m] ? ram[m] : 0;
        }

        // GEMM1: D1[16px x 48f] per m, A frags direct from x copies
        float d1[2][6][4];
        #pragma unroll
        for (int m = 0; m < 2; m++)
            #pragma unroll
            for (int n = 0; n < 6; n++)
                #pragma unroll
                for (int e = 0; e < 4; e++) d1[m][n][e] = 0.f;
        #pragma unroll
        for (int k = 0; k < 4; k++) {
            uint32_t afr[2][4];
            #pragma unroll
            for (int m = 0; m < 2; m++) {
                const char* ab = xcp + (((ramc[m] + 2 * k) * XSTR) + colB[m]) * 2;
                afr[m][0] = *(const uint32_t*)ab;
                afr[m][1] = *(const uint32_t*)(ab + 16);
                if (k < 3) {
                    afr[m][2] = *(const uint32_t*)(ab + 2 * XSTR);
                    afr[m][3] = *(const uint32_t*)(ab + 2 * XSTR + 16);
                } else {
                    afr[m][2] = 0u; afr[m][3] = 0u;   // k>=56 hits zero B cols
                }
            }
            #pragma unroll
            for (int n = 0; n < 6; n++) {
                uint2 b01 = bp1[(k * 6 + n) * 32];
                mma_bf16(d1[0][n], afr[0], b01.x, b01.y);
                mma_bf16(d1[1][n], afr[1], b01.x, b01.y);
            }
        }

        // RBF via nearest-neighbor u16 table (+ zero outside image)
        #pragma unroll
        for (int m = 0; m < 2; m++) {
            int u = y0 - 3 + ram[m];
            bool uok = (u >= 0) && (u < IMG);
            int vA = x0 - 3 + cbm[m] + g;
            int vB = vA + 8;
            bool okA = uok && (vA >= 0) && (vA < IMG);
            bool okB = uok && (vB >= 0) && (vB < IMG);
            #pragma unroll
            for (int n = 0; n < 6; n++) {
                #pragma unroll
                for (int e = 0; e < 4; e++) {
                    bool okp = (e < 2) ? okA : okB;
                    int fidx = n * 8 + tg * 2 + (e & 1);
                    float z = d1[m][n][e];
                    float t = fminf(fmaxf((z + 8.f) * 64.f, 0.f), 1024.f);
                    int ix = __float2int_rn(t);
                    uint32_t tv = (uint32_t)__ldg(&g_tabn[fidx * TABN + ix]);
                    float a = __uint_as_float(tv << 16);
                    d1[m][n][e] = okp ? a : 0.f;
                }
            }
        }

        // repack D1 -> A fragments of GEMM2 (register-only)
        uint32_t a2[2][3][4];
        #pragma unroll
        for (int m = 0; m < 2; m++)
            #pragma unroll
            for (int t = 0; t < 3; t++) {
                a2[m][t][0] = bfpk(d1[m][2 * t][1],     d1[m][2 * t][0]);
                a2[m][t][1] = bfpk(d1[m][2 * t][3],     d1[m][2 * t][2]);
                a2[m][t][2] = bfpk(d1[m][2 * t + 1][1], d1[m][2 * t + 1][0]);
                a2[m][t][3] = bfpk(d1[m][2 * t + 1][3], d1[m][2 * t + 1][2]);
            }

        char* grow[2];
        #pragma unroll
        for (int m = 0; m < 2; m++)
            grow[m] = smem + G_OFF + (ram[m] & 15) * GROWR;

        // GEMM2 half 1: n = 0..3
        {
            float d2[2][4][4];
            #pragma unroll
            for (int m = 0; m < 2; m++)
                #pragma unroll
                for (int n = 0; n < 4; n++)
                    #pragma unroll
                    for (int e = 0; e < 4; e++) d2[m][n][e] = 0.f;
            #pragma unroll
            for (int k = 0; k < 3; k++) {
                #pragma unroll
                for (int n = 0; n < 4; n++) {
                    uint2 b01 = bp2[(k * 7 + n) * 32];
                    mma_bf16(d2[0][n], a2[0][k], b01.x, b01.y);
                    mma_bf16(d2[1][n], a2[1][k], b01.x, b01.y);
                }
            }
            #pragma unroll
            for (int m = 0; m < 2; m++) {
                if (ok[m]) {
                    int pxA = cbm[m] + g;
                    #pragma unroll
                    for (int n = 0; n < 4; n++) {
                        uint32_t lo = bfpk(d2[m][n][1], d2[m][n][0]);
                        uint32_t hi = bfpk(d2[m][n][3], d2[m][n][2]);
                        int noff = (n * 8 + tg * 2) * 2;
                        *(uint32_t*)(grow[m] + pxA * GPX + noff) = lo;
                        *(uint32_t*)(grow[m] + (pxA + 8) * GPX + noff) = hi;
                    }
                }
            }
        }
        // GEMM2 half 2: n = 4..6
        {
            float d2[2][3][4];
            #pragma unroll
            for (int m = 0; m < 2; m++)
                #pragma unroll
                for (int n = 0; n < 3; n++)
                    #pragma unroll
                    for (int e = 0; e < 4; e++) d2[m][n][e] = 0.f;
            #pragma unroll
            for (int k = 0; k < 3; k++) {
                #pragma unroll
                for (int n = 0; n < 3; n++) {
                    uint2 b01 = bp2[(k * 7 + n + 4) * 32];
                    mma_bf16(d2[0][n], a2[0][k], b01.x, b01.y);
                    mma_bf16(d2[1][n], a2[1][k], b01.x, b01.y);
                }
            }
            #pragma unroll
            for (int m = 0; m < 2; m++) {
                if (ok[m]) {
                    int pxA = cbm[m] + g;
                    #pragma unroll
                    for (int n = 0; n < 3; n++) {
                        uint32_t lo = bfpk(d2[m][n][1], d2[m][n][0]);
                        uint32_t hi = bfpk(d2[m][n][3], d2[m][n][2]);
                        int noff = ((n + 4) * 8 + tg * 2) * 2;
                        *(uint32_t*)(grow[m] + pxA * GPX + noff) = lo;
                        *(uint32_t*)(grow[m] + (pxA + 8) * GPX + noff) = hi;
                    }
                }
            }
        }

        __syncthreads();   // G for slab s complete

        // ---- gather: col2im + residual for out rows 8(s-1)..8(s-1)+7 ----
        if (s >= 1) {
            int yl = 8 * (s - 1) + yh;
            int xg = x0 + xl;
            if (xl < 42 && xg < IMG) {
                float cv = 0.f;
                #pragma unroll
                for (int p = 0; p < 7; p++) {
                    const char* rb = smem + G_OFF + ((yl + 6 - p) & 15) * GROWR + p * 16;
                    #pragma unroll
                    for (int q = 0; q < 7; q++) {
                        uint16_t gv = *(const uint16_t*)(rb + (xl + 6 - q) * GPX + q * 2);
                        cv += __uint_as_float((uint32_t)gv << 16);
                    }
                }
                int yg = y0 + yl;
                float iv = ibase[yg * IMG + xg];
                float nv = nbase[yg * IMG + xg];
                float rv = iv - cv - nv;
                g_r[img * IMG * IMG + yg * IMG + xg] = rv;
                ss += rv * rv;
            }
        }
    }

    __syncthreads();
    float* red = (float*)(smem + RED_OFF);
    #pragma unroll
    for (int o = 16; o > 0; o >>= 1) ss += __shfl_down_sync(0xffffffffu, ss, o);
    if (lane == 0) red[wid] = ss;
    __syncthreads();
    if (tid == 0) {
        float t = 0.f;
        #pragma unroll
        for (int w = 0; w < 12; w++) t += red[w];
        g_partial[img * 56 + rr] = t;
    }
}

// ---------------- K3: scale + out = net_input + r*scale ----------------
__global__ void final_kernel(const float* __restrict__ net_input,
                             const float* __restrict__ stdn,
                             const float* __restrict__ alpha,
                             float* __restrict__ out) {
    __shared__ float sc_sh;
    int v = blockIdx.x * blockDim.x + threadIdx.x;  // float4 index
    int b = v >> 14;
    if (threadIdx.x == 0) {
        float s = 0.f;
        #pragma unroll
        for (int t = 0; t < 56; t++) s += g_partial[b * 56 + t];
        float nr = sqrtf(s);
        float k = expf(alpha[0]) * stdn[b] * 256.f;
        sc_sh = fminf(1.f, k / (nr + 1e-12f));
    }
    __syncthreads();
    float sc = sc_sh;
    float4 rr = ((const float4*)g_r)[v];
    float4 nn = ((const float4*)net_input)[v];
    float4 o;
    o.x = nn.x + rr.x * sc;
    o.y = nn.y + rr.y * sc;
    o.z = nn.z + rr.z * sc;
    o.w = nn.w + rr.w * sc;
    ((float4*)out)[v] = o;
}

extern "C" void kernel_launch(void* const* d_in, const int* in_sizes, int n_in,
                              void* d_out, int out_size) {
    const float* input     = (const float*)d_in[0];
    const float* stdn      = (const float*)d_in[1];
    const float* net_input = (const float*)d_in[3];
    const float* cw        = (const float*)d_in[4];
    const float* sf        = (const float*)d_in[5];
    const float* alpha     = (const float*)d_in[6];
    const float* rbw       = (const float*)d_in[7];
    const float* rbc       = (const float*)d_in[8];
    float* out = (float*)d_out;

    cudaFuncSetAttribute(main_kernel, cudaFuncAttributeMaxDynamicSharedMemorySize, SMEM_TOTAL);

    prep_kernel<<<NF, 256>>>(cw, sf, rbw, rbc);
    pack_kernel<<<1, 768>>>();
    dummy_kernel<<<1, 32>>>();
    main_kernel<<<896, 384, SMEM_TOTAL>>>(input, net_input);
    final_kernel<<<1024, 256>>>(net_input, stdn, alpha, out);
}